// round 16
// baseline (speedup 1.0000x reference)
#include <cuda_runtime.h>
#include <cuda_fp16.h>
#include <math.h>
#include <stdint.h>

#define N_IMG   4
#define C       256
#define HW      4096
#define THREE_C 768

// Scratch (device globals: allocation-free rule)
__device__ float g_scale[C];
__device__ float g_shift[C];
__device__ __align__(16) __half g_seq_h[N_IMG * HW * C];
__device__ __align__(16) __half g_qkv_h[N_IMG * HW * THREE_C];
__device__ __align__(16) __half g_o_h[N_IMG * HW * C];
__device__ __align__(16) __half g_wq_h[C * THREE_C];
__device__ __align__(16) __half g_wp_h[C * C];

__device__ __forceinline__ uint32_t smem_u32(const void* p) {
    uint32_t a;
    asm("{ .reg .u64 t; cvta.to.shared.u64 t, %1; cvt.u32.u64 %0, t; }"
        : "=r"(a) : "l"(p));
    return a;
}
__device__ __forceinline__ uint32_t f2h2(float lo, float hi) {
    uint32_t u;
    asm("cvt.rn.f16x2.f32 %0, %1, %2;" : "=r"(u) : "f"(hi), "f"(lo));
    return u;
}
__device__ __forceinline__ void mma16(float* d, const uint32_t* a,
                                      uint32_t b0, uint32_t b1) {
    asm volatile(
        "mma.sync.aligned.m16n8k16.row.col.f32.f16.f16.f32 "
        "{%0,%1,%2,%3}, {%4,%5,%6,%7}, {%8,%9}, {%0,%1,%2,%3};"
        : "+f"(d[0]), "+f"(d[1]), "+f"(d[2]), "+f"(d[3])
        : "r"(a[0]), "r"(a[1]), "r"(a[2]), "r"(a[3]), "r"(b0), "r"(b1));
}
__device__ __forceinline__ void ldsm4(uint32_t* r, uint32_t a) {
    asm volatile("ldmatrix.sync.aligned.m8n8.x4.shared.b16 {%0,%1,%2,%3}, [%4];"
                 : "=r"(r[0]), "=r"(r[1]), "=r"(r[2]), "=r"(r[3]) : "r"(a));
}
__device__ __forceinline__ void ldsm4t(uint32_t* r, uint32_t a) {
    asm volatile("ldmatrix.sync.aligned.m8n8.x4.trans.shared.b16 {%0,%1,%2,%3}, [%4];"
                 : "=r"(r[0]), "=r"(r[1]), "=r"(r[2]), "=r"(r[3]) : "r"(a));
}
__device__ __forceinline__ void cpa16(uint32_t dst, const void* src) {
    asm volatile("cp.async.ca.shared.global [%0], [%1], 16;"
                 :: "r"(dst), "l"(src));
}
#define CPA_COMMIT() asm volatile("cp.async.commit_group;" ::: "memory")
#define CPA_WAIT1()  asm volatile("cp.async.wait_group 1;" ::: "memory")
#define CPA_WAIT0()  asm volatile("cp.async.wait_group 0;" ::: "memory")

// ===========================================================================
// fp16 GEMM core (R9 config): BM=128, BN=128, BK=32, 256 threads (8 warps,
// 4m x 2n), warp-tile 32x64, 3-stage cp.async pipeline.
// ===========================================================================
#define GA_PITCH 40
#define GB_PITCH 136
#define GB_OFF   (128 * GA_PITCH * 2)                // 10240 B (A stage)
#define GST      (GB_OFF + 32 * GB_PITCH * 2)        // 18944 B per stage
#define QK_SMEM  (3 * GST)                           // 56832 B
#define PJ_SMEM  (128 * 132 * 4)                     // 67584 B (proj staging)

// ---- QKV GEMM: (16384 x 256) @ (256 x 768) -> g_qkv_h, grid (6, 128) ----
__global__ __launch_bounds__(256) void gemm_qkv_h() {
    extern __shared__ __align__(16) char smem[];
    const uint32_t sb = smem_u32(smem);
    const int t = threadIdx.x, w = t >> 5, lane = t & 31;
    const int sub = lane >> 3, g = lane >> 2, tg = lane & 3;
    const int wr = w >> 1, wc = w & 1;
    const int m0 = blockIdx.y * 128, n0 = blockIdx.x * 128;

    const uint32_t a_off =
        ((wr * 32 + (sub & 1) * 8 + (lane & 7)) * GA_PITCH + (sub >> 1) * 8) * 2;
    const uint32_t b_off = GB_OFF +
        (((sub & 1) * 8 + (lane & 7)) * GB_PITCH + wc * 64 + (sub >> 1) * 8) * 2;

    const __half* Ag = g_seq_h + (size_t)m0 * 256;
    const int arow = t >> 1, acq = (t & 1) * 16;
    const int brow = t >> 3, bcq = (t & 7) * 16;

#define QKV_COPY(stg, kk)                                                      \
    do {                                                                       \
        uint32_t sbase = sb + (stg) * GST;                                     \
        cpa16(sbase + (arow * GA_PITCH + acq) * 2,                             \
              &Ag[arow * 256 + (kk) + acq]);                                   \
        cpa16(sbase + (arow * GA_PITCH + acq + 8) * 2,                         \
              &Ag[arow * 256 + (kk) + acq + 8]);                               \
        cpa16(sbase + GB_OFF + (brow * GB_PITCH + bcq) * 2,                    \
              &g_wq_h[((kk) + brow) * 768 + n0 + bcq]);                        \
        cpa16(sbase + GB_OFF + (brow * GB_PITCH + bcq + 8) * 2,                \
              &g_wq_h[((kk) + brow) * 768 + n0 + bcq + 8]);                    \
    } while (0)

    QKV_COPY(0, 0);
    CPA_COMMIT();

    float acc[2][8][4] = {};
    int cur = 0;
    for (int ki = 0; ki < 8; ki++) {
        int nxt = cur + 1; if (nxt == 3) nxt = 0;
        if (ki < 7) {
            QKV_COPY(nxt, (ki + 1) * 32);
            CPA_COMMIT();
            CPA_WAIT1();
        } else {
            CPA_WAIT0();
        }
        __syncthreads();
        const uint32_t abase = sb + cur * GST + a_off;
        const uint32_t bbase = sb + cur * GST + b_off;
#pragma unroll
        for (int ks = 0; ks < 2; ks++) {
            uint32_t a0[4], a1[4];
            ldsm4(a0, abase + ks * 32);
            ldsm4(a1, abase + 16 * GA_PITCH * 2 + ks * 32);
#pragma unroll
            for (int ntp = 0; ntp < 4; ntp++) {
                uint32_t vb[4];
                ldsm4t(vb, bbase + ks * 16 * GB_PITCH * 2 + ntp * 32);
                mma16(acc[0][2 * ntp],     a0, vb[0], vb[1]);
                mma16(acc[0][2 * ntp + 1], a0, vb[2], vb[3]);
                mma16(acc[1][2 * ntp],     a1, vb[0], vb[1]);
                mma16(acc[1][2 * ntp + 1], a1, vb[2], vb[3]);
            }
        }
        cur = nxt;
    }
#pragma unroll
    for (int mt = 0; mt < 2; mt++)
#pragma unroll
        for (int nt = 0; nt < 8; nt++) {
            int row = m0 + wr * 32 + mt * 16 + g;
            int col = n0 + wc * 64 + nt * 8 + 2 * tg;
            *(uint32_t*)&g_qkv_h[(size_t)row * 768 + col] =
                f2h2(acc[mt][nt][0], acc[mt][nt][1]);
            *(uint32_t*)&g_qkv_h[(size_t)(row + 8) * 768 + col] =
                f2h2(acc[mt][nt][2], acc[mt][nt][3]);
        }
}

// ---- Proj GEMM: (16384 x 256) @ (256 x 256) + b -> out NCHW, grid (2, 128) ----
__global__ __launch_bounds__(256) void gemm_proj_h(const float* __restrict__ bias,
                                                   float* __restrict__ out) {
    extern __shared__ __align__(16) char smem[];
    const uint32_t sb = smem_u32(smem);
    const int t = threadIdx.x, w = t >> 5, lane = t & 31;
    const int sub = lane >> 3, g = lane >> 2, tg = lane & 3;
    const int wr = w >> 1, wc = w & 1;
    const int m0 = blockIdx.y * 128, n0 = blockIdx.x * 128;

    const uint32_t a_off =
        ((wr * 32 + (sub & 1) * 8 + (lane & 7)) * GA_PITCH + (sub >> 1) * 8) * 2;
    const uint32_t b_off = GB_OFF +
        (((sub & 1) * 8 + (lane & 7)) * GB_PITCH + wc * 64 + (sub >> 1) * 8) * 2;

    const __half* Ag = g_o_h + (size_t)m0 * 256;
    const int arow = t >> 1, acq = (t & 1) * 16;
    const int brow = t >> 3, bcq = (t & 7) * 16;

#define PJ_COPY(stg, kk)                                                       \
    do {                                                                       \
        uint32_t sbase = sb + (stg) * GST;                                     \
        cpa16(sbase + (arow * GA_PITCH + acq) * 2,                             \
              &Ag[arow * 256 + (kk) + acq]);                                   \
        cpa16(sbase + (arow * GA_PITCH + acq + 8) * 2,                         \
              &Ag[arow * 256 + (kk) + acq + 8]);                               \
        cpa16(sbase + GB_OFF + (brow * GB_PITCH + bcq) * 2,                    \
              &g_wp_h[((kk) + brow) * 256 + n0 + bcq]);                        \
        cpa16(sbase + GB_OFF + (brow * GB_PITCH + bcq + 8) * 2,                \
              &g_wp_h[((kk) + brow) * 256 + n0 + bcq + 8]);                    \
    } while (0)

    PJ_COPY(0, 0);
    CPA_COMMIT();

    float acc[2][8][4] = {};
    int cur = 0;
    for (int ki = 0; ki < 8; ki++) {
        int nxt = cur + 1; if (nxt == 3) nxt = 0;
        if (ki < 7) {
            PJ_COPY(nxt, (ki + 1) * 32);
            CPA_COMMIT();
            CPA_WAIT1();
        } else {
            CPA_WAIT0();
        }
        __syncthreads();
        const uint32_t abase = sb + cur * GST + a_off;
        const uint32_t bbase = sb + cur * GST + b_off;
#pragma unroll
        for (int ks = 0; ks < 2; ks++) {
            uint32_t a0[4], a1[4];
            ldsm4(a0, abase + ks * 32);
            ldsm4(a1, abase + 16 * GA_PITCH * 2 + ks * 32);
#pragma unroll
            for (int ntp = 0; ntp < 4; ntp++) {
                uint32_t vb[4];
                ldsm4t(vb, bbase + ks * 16 * GB_PITCH * 2 + ntp * 32);
                mma16(acc[0][2 * ntp],     a0, vb[0], vb[1]);
                mma16(acc[0][2 * ntp + 1], a0, vb[2], vb[3]);
                mma16(acc[1][2 * ntp],     a1, vb[0], vb[1]);
                mma16(acc[1][2 * ntp + 1], a1, vb[2], vb[3]);
            }
        }
        cur = nxt;
    }
    __syncthreads();

    // stage [c][m+pad] fp32 for coalesced transposed store
    float* st = (float*)smem;
#pragma unroll
    for (int mt = 0; mt < 2; mt++)
#pragma unroll
        for (int nt = 0; nt < 8; nt++) {
            int rl = wr * 32 + mt * 16 + g;
            int cl = wc * 64 + nt * 8 + 2 * tg;
            st[cl * 132 + rl]           = acc[mt][nt][0];
            st[(cl + 1) * 132 + rl]     = acc[mt][nt][1];
            st[cl * 132 + rl + 8]       = acc[mt][nt][2];
            st[(cl + 1) * 132 + rl + 8] = acc[mt][nt][3];
        }
    __syncthreads();

    const int ml = t & 31, wi = t >> 5;
    const int nimg = m0 >> 12, pbase = m0 & 4095;
#pragma unroll
    for (int i = 0; i < 16; i++) {
        int cl = wi + 8 * i;
        float bb = bias[n0 + cl];
        float* orow = out + ((size_t)(nimg * C + n0 + cl)) * HW + pbase;
#pragma unroll
        for (int ch = 0; ch < 4; ch++)
            orow[ml + 32 * ch] = st[cl * 132 + ml + 32 * ch] + bb;
    }
}

// ===========================================================================
// fp16 flash attention: q-tile 64, 2 warps (64 threads), 2-stage cp.async
// K/V pipeline (copy-after-barrier), 5 CTAs/SM. Register-resident P,
// S/exp/PV software pipeline, Q pre-scaled by 1/8.
// ===========================================================================
#define KV_STG   18432
#define SMEM_ATTN_B (2 * KV_STG)       // 36864 -> 5 CTAs/SM (184KB)

__global__ __launch_bounds__(64, 5) void attn_mma() {
    extern __shared__ char smraw[];
    const uint32_t sb = smem_u32(smraw);

    const int t    = threadIdx.x;      // 0..63
    const int lane = t & 31;
    const int g    = lane >> 2;
    const int tg   = lane & 3;
    const int rb   = (t >> 5) * 32;

    const int qt = blockIdx.x;         // 0..63 (q-tiles of 64)
    const int nh = blockIdx.y;
    const int n  = nh >> 2, h = nh & 3;
    const __half* qkvh = g_qkv_h + (size_t)n * HW * THREE_C;

    const int rowl = t >> 3;          // copy row lane 0..7
    const int c8   = (t & 7) * 8;     // copy column (8 halfs = 16 B)

    const uint32_t sub = lane >> 3;
    const uint32_t kf_off = ((((sub >> 1) * 8) + (lane & 7)) * 72 + (sub & 1) * 8) * 2;
    const uint32_t vf_off = 9216 +
        ((((sub & 1) * 8) + (lane & 7)) * 72 + (sub >> 1) * 8) * 2;

#define ATTN_COPY(stg, kt_)                                                    \
    do {                                                                       \
        uint32_t sbase = sb + (stg) * KV_STG;                                  \
        _Pragma("unroll")                                                      \
        for (int i_ = 0; i_ < 8; i_++) {                                       \
            int row_ = rowl + 8 * i_;                                          \
            int rg_  = (kt_) * 64 + row_;                                      \
            int p_   = h * 1024 + (rg_ >> 2);                                  \
            int s_   = rg_ & 3;                                                \
            const __half* base_ = qkvh + (size_t)p_ * 768 + s_ * 192;          \
            cpa16(sbase + (row_ * 72 + c8) * 2, base_ + 64 + c8);              \
            cpa16(sbase + 9216 + (row_ * 72 + c8) * 2, base_ + 128 + c8);      \
        }                                                                      \
    } while (0)

    // Q A-frags in registers, pre-scaled by 1/8 (exact power of 2 in fp16)
    uint32_t aq[2][4][4];
    {
        const __half2 kEighth = __floats2half2_rn(0.125f, 0.125f);
#pragma unroll
        for (int mt = 0; mt < 2; mt++)
#pragma unroll
            for (int rr = 0; rr < 2; rr++) {
                int r  = qt * 64 + rb + mt * 16 + rr * 8 + g;
                int p  = h * 1024 + (r >> 2);
                int s  = r & 3;
                const __half* qrow = qkvh + (size_t)p * 768 + s * 192;
#pragma unroll
                for (int ks = 0; ks < 4; ks++) {
                    __half2 v0 = *(const __half2*)&qrow[ks * 16 + 2 * tg];
                    __half2 v1 = *(const __half2*)&qrow[ks * 16 + 8 + 2 * tg];
                    v0 = __hmul2(v0, kEighth);
                    v1 = __hmul2(v1, kEighth);
                    aq[mt][ks][rr]     = *(uint32_t*)&v0;
                    aq[mt][ks][rr + 2] = *(uint32_t*)&v1;
                }
            }
    }

    ATTN_COPY(0, 0);
    CPA_COMMIT();

    float co[2][8][4] = {};
    float lsum[2][2]  = {};

    int cur = 0;
    for (int kt = 0; kt < 64; kt++) {
        CPA_WAIT0();
        __syncthreads();                // tile kt in buffer cur; old reads done
        if (kt < 63) {
            ATTN_COPY(cur ^ 1, kt + 1); // WAR-safe: all warps past barrier
            CPA_COMMIT();
        }

        const uint32_t kfb = sb + cur * KV_STG + kf_off;
        const uint32_t vfb = sb + cur * KV_STG + vf_off;

        uint32_t pa[2][4][4];
        float s00[4], s01[4], s10[4], s11[4];

#define S_BLK(j)                                                               \
    do {                                                                       \
        _Pragma("unroll")                                                      \
        for (int i_ = 0; i_ < 4; i_++) {                                       \
            s00[i_] = 0.f; s01[i_] = 0.f; s10[i_] = 0.f; s11[i_] = 0.f;        \
        }                                                                      \
        _Pragma("unroll")                                                      \
        for (int ks_ = 0; ks_ < 4; ks_++) {                                    \
            uint32_t kb_[4];                                                   \
            ldsm4(kb_, kfb + (j) * 2304 + ks_ * 32);                           \
            mma16(s00, aq[0][ks_], kb_[0], kb_[1]);                            \
            mma16(s01, aq[0][ks_], kb_[2], kb_[3]);                            \
            mma16(s10, aq[1][ks_], kb_[0], kb_[1]);                            \
            mma16(s11, aq[1][ks_], kb_[2], kb_[3]);                            \
        }                                                                      \
    } while (0)

#define EXP_BLK(j)                                                             \
    do {                                                                       \
        float a0 = __expf(s00[0]), a1 = __expf(s00[1]);                        \
        float a2 = __expf(s00[2]), a3 = __expf(s00[3]);                        \
        float b0 = __expf(s01[0]), b1 = __expf(s01[1]);                        \
        float b2 = __expf(s01[2]), b3 = __expf(s01[3]);                        \
        lsum[0][0] += (a0 + a1) + (b0 + b1);                                   \
        lsum[0][1] += (a2 + a3) + (b2 + b3);                                   \
        pa[0][j][0] = f2h2(a0, a1);                                            \
        pa[0][j][1] = f2h2(a2, a3);                                            \
        pa[0][j][2] = f2h2(b0, b1);                                            \
        pa[0][j][3] = f2h2(b2, b3);                                            \
        float c0 = __expf(s10[0]), c1 = __expf(s10[1]);                        \
        float c2 = __expf(s10[2]), c3 = __expf(s10[3]);                        \
        float d0 = __expf(s11[0]), d1 = __expf(s11[1]);                        \
        float d2 = __expf(s11[2]), d3 = __expf(s11[3]);                        \
        lsum[1][0] += (c0 + c1) + (d0 + d1);                                   \
        lsum[1][1] += (c2 + c3) + (d2 + d3);                                   \
        pa[1][j][0] = f2h2(c0, c1);                                            \
        pa[1][j][1] = f2h2(c2, c3);                                            \
        pa[1][j][2] = f2h2(d0, d1);                                            \
        pa[1][j][3] = f2h2(d2, d3);                                            \
    } while (0)

#define PV_BLK(j)                                                              \
    do {                                                                       \
        _Pragma("unroll")                                                      \
        for (int ntp_ = 0; ntp_ < 4; ntp_++) {                                 \
            uint32_t vb_[4];                                                   \
            ldsm4t(vb_, vfb + (j) * 2304 + ntp_ * 32);                         \
            mma16(co[0][2 * ntp_],     pa[0][j], vb_[0], vb_[1]);              \
            mma16(co[0][2 * ntp_ + 1], pa[0][j], vb_[2], vb_[3]);              \
            mma16(co[1][2 * ntp_],     pa[1][j], vb_[0], vb_[1]);              \
            mma16(co[1][2 * ntp_ + 1], pa[1][j], vb_[2], vb_[3]);              \
        }                                                                      \
    } while (0)

        S_BLK(0); EXP_BLK(0);
        S_BLK(1); PV_BLK(0); EXP_BLK(1);
        S_BLK(2); PV_BLK(1); EXP_BLK(2);
        S_BLK(3); PV_BLK(2); EXP_BLK(3);
        PV_BLK(3);

        cur ^= 1;
    }

    // finalize: quad row-sum reduce, normalize, stage as half, store
    float inv[2][2];
#pragma unroll
    for (int mt = 0; mt < 2; mt++)
#pragma unroll
        for (int hh = 0; hh < 2; hh++) {
            float l = lsum[mt][hh];
            l += __shfl_xor_sync(0xffffffffu, l, 1);
            l += __shfl_xor_sync(0xffffffffu, l, 2);
            inv[mt][hh] = 1.f / l;
        }
    __syncthreads();   // done with K/V smem; reuse as half staging [64][80]
#pragma unroll
    for (int mt = 0; mt < 2; mt++) {
        int r0 = rb + mt * 16 + g;
#pragma unroll
        for (int nt = 0; nt < 8; nt++) {
            *(uint32_t*)(smraw + (r0 * 80 + nt * 8 + 2 * tg) * 2) =
                f2h2(co[mt][nt][0] * inv[mt][0], co[mt][nt][1] * inv[mt][0]);
            *(uint32_t*)(smraw + ((r0 + 8) * 80 + nt * 8 + 2 * tg) * 2) =
                f2h2(co[mt][nt][2] * inv[mt][1], co[mt][nt][3] * inv[mt][1]);
        }
    }
    __syncthreads();
    {
        int rg = qt * 64 + t;
        int p  = h * 1024 + (rg >> 2);
        int s  = rg & 3;
        __half* dst = g_o_h + ((size_t)n * HW + p) * C + s * 64;
#pragma unroll
        for (int j = 0; j < 8; j++)
            *(uint4*)&dst[8 * j] = *(uint4*)(smraw + (t * 80 + 8 * j) * 2);
    }
}

// ---------------------------------------------------------------------------
// BatchNorm statistics -> per-channel scale/shift
// ---------------------------------------------------------------------------
__global__ void bn_stats(const float* __restrict__ x,
                         const float* __restrict__ gamma,
                         const float* __restrict__ beta) {
    int c = blockIdx.x;
    int t = threadIdx.x;
    float s = 0.f, s2 = 0.f;
    for (int n = 0; n < N_IMG; n++) {
        const float* p = x + ((size_t)n * C + c) * HW;
        for (int i = t; i < HW; i += 256) {
            float v = p[i];
            s += v;
            s2 += v * v;
        }
    }
    __shared__ float sh0[256], sh1[256];
    sh0[t] = s; sh1[t] = s2;
    __syncthreads();
    for (int o = 128; o > 0; o >>= 1) {
        if (t < o) { sh0[t] += sh0[t + o]; sh1[t] += sh1[t + o]; }
        __syncthreads();
    }
    if (t == 0) {
        const float inv = 1.f / (float)(N_IMG * HW);
        float mean = sh0[0] * inv;
        float var  = sh1[0] * inv - mean * mean;
        float rstd = rsqrtf(var + 1e-5f);
        float sc   = gamma[c] * rstd;
        g_scale[c] = sc;
        g_shift[c] = beta[c] - mean * sc;
    }
}

// ---------------------------------------------------------------------------
// Normalize + transpose (n,c,hw) -> (n,hw,c) as half (half2 stores)
// ---------------------------------------------------------------------------
__global__ void norm_transpose(const float* __restrict__ x) {
    __shared__ float tile[32][33];
    int n  = blockIdx.z;
    int c0 = blockIdx.y * 32;
    int p0 = blockIdx.x * 32;
    int tx = threadIdx.x, ty = threadIdx.y;  // 32 x 8
    int t  = ty * 32 + tx;                   // 0..255
#pragma unroll
    for (int j = 0; j < 4; j++) {
        int c = c0 + ty + j * 8;
        tile[ty + j * 8][tx] =
            x[((size_t)n * C + c) * HW + p0 + tx] * g_scale[c] + g_shift[c];
    }
    __syncthreads();
#pragma unroll
    for (int it = 0; it < 2; it++) {
        int e   = it * 256 + t;
        int pos = e >> 4;
        int cp  = e & 15;
        *(uint32_t*)&g_seq_h[((size_t)n * HW + p0 + pos) * C + c0 + 2 * cp] =
            f2h2(tile[2 * cp][pos], tile[2 * cp + 1][pos]);
    }
}

// ---------------------------------------------------------------------------
// Weight pre-conversion (once per launch; deterministic)
// ---------------------------------------------------------------------------
__global__ void convert_w(const float* __restrict__ qkv_w,
                          const float* __restrict__ proj_w) {
    int i = blockIdx.x * 256 + threadIdx.x;
    if (i < C * THREE_C) g_wq_h[i] = __float2half_rn(qkv_w[i]);
    int j = i - C * THREE_C;
    if (j >= 0 && j < C * C) g_wp_h[j] = __float2half_rn(proj_w[j]);
}

// ---------------------------------------------------------------------------
extern "C" void kernel_launch(void* const* d_in, const int* in_sizes, int n_in,
                              void* d_out, int out_size) {
    const float* x      = (const float*)d_in[0];
    const float* gamma  = (const float*)d_in[1];
    const float* beta   = (const float*)d_in[2];
    const float* qkv_w  = (const float*)d_in[3];
    const float* proj_w = (const float*)d_in[4];
    const float* proj_b = (const float*)d_in[5];
    float* out = (float*)d_out;

    cudaFuncSetAttribute(gemm_qkv_h,
                         cudaFuncAttributeMaxDynamicSharedMemorySize, QK_SMEM);
    cudaFuncSetAttribute(gemm_proj_h,
                         cudaFuncAttributeMaxDynamicSharedMemorySize, PJ_SMEM);
    cudaFuncSetAttribute(attn_mma,
                         cudaFuncAttributeMaxDynamicSharedMemorySize, SMEM_ATTN_B);

    bn_stats<<<256, 256>>>(x, gamma, beta);
    norm_transpose<<<dim3(128, 8, 4), dim3(32, 8)>>>(x);
    convert_w<<<(C * THREE_C + C * C) / 256, 256>>>(qkv_w, proj_w);
    gemm_qkv_h<<<dim3(6, 128), 256, QK_SMEM>>>();
    attn_mma<<<dim3(64, 16), 64, SMEM_ATTN_B>>>();
    gemm_proj_h<<<dim3(2, 128), 256, PJ_SMEM>>>(proj_b, out);
}

// round 17
// speedup vs baseline: 1.1184x; 1.1184x over previous
#include <cuda_runtime.h>
#include <cuda_fp16.h>
#include <math.h>
#include <stdint.h>

#define N_IMG   4
#define C       256
#define HW      4096
#define THREE_C 768

// Scratch (device globals: allocation-free rule)
__device__ float g_scale[C];
__device__ float g_shift[C];
__device__ __align__(16) __half g_seq_h[N_IMG * HW * C];
__device__ __align__(16) __half g_qkv_h[N_IMG * HW * THREE_C];
__device__ __align__(16) __half g_o_h[N_IMG * HW * C];
__device__ __align__(16) __half g_wq_h[C * THREE_C];
__device__ __align__(16) __half g_wp_h[C * C];

__device__ __forceinline__ uint32_t smem_u32(const void* p) {
    uint32_t a;
    asm("{ .reg .u64 t; cvta.to.shared.u64 t, %1; cvt.u32.u64 %0, t; }"
        : "=r"(a) : "l"(p));
    return a;
}
__device__ __forceinline__ uint32_t f2h2(float lo, float hi) {
    uint32_t u;
    asm("cvt.rn.f16x2.f32 %0, %1, %2;" : "=r"(u) : "f"(hi), "f"(lo));
    return u;
}
__device__ __forceinline__ void mma16(float* d, const uint32_t* a,
                                      uint32_t b0, uint32_t b1) {
    asm volatile(
        "mma.sync.aligned.m16n8k16.row.col.f32.f16.f16.f32 "
        "{%0,%1,%2,%3}, {%4,%5,%6,%7}, {%8,%9}, {%0,%1,%2,%3};"
        : "+f"(d[0]), "+f"(d[1]), "+f"(d[2]), "+f"(d[3])
        : "r"(a[0]), "r"(a[1]), "r"(a[2]), "r"(a[3]), "r"(b0), "r"(b1));
}
__device__ __forceinline__ void ldsm4(uint32_t* r, uint32_t a) {
    asm volatile("ldmatrix.sync.aligned.m8n8.x4.shared.b16 {%0,%1,%2,%3}, [%4];"
                 : "=r"(r[0]), "=r"(r[1]), "=r"(r[2]), "=r"(r[3]) : "r"(a));
}
__device__ __forceinline__ void ldsm4t(uint32_t* r, uint32_t a) {
    asm volatile("ldmatrix.sync.aligned.m8n8.x4.trans.shared.b16 {%0,%1,%2,%3}, [%4];"
                 : "=r"(r[0]), "=r"(r[1]), "=r"(r[2]), "=r"(r[3]) : "r"(a));
}
__device__ __forceinline__ void cpa16(uint32_t dst, const void* src) {
    asm volatile("cp.async.ca.shared.global [%0], [%1], 16;"
                 :: "r"(dst), "l"(src));
}
#define CPA_COMMIT() asm volatile("cp.async.commit_group;" ::: "memory")
#define CPA_WAIT1()  asm volatile("cp.async.wait_group 1;" ::: "memory")
#define CPA_WAIT0()  asm volatile("cp.async.wait_group 0;" ::: "memory")

// ===========================================================================
// fp16 GEMM core (R9 config): BM=128, BN=128, BK=32, 256 threads (8 warps,
// 4m x 2n), warp-tile 32x64, 3-stage cp.async pipeline.
// ===========================================================================
#define GA_PITCH 40
#define GB_PITCH 136
#define GB_OFF   (128 * GA_PITCH * 2)                // 10240 B (A stage)
#define GST      (GB_OFF + 32 * GB_PITCH * 2)        // 18944 B per stage
#define QK_SMEM  (3 * GST)                           // 56832 B
#define PJ_SMEM  (128 * 132 * 4)                     // 67584 B (proj staging)

// ---- QKV GEMM: (16384 x 256) @ (256 x 768) -> g_qkv_h, grid (6, 128) ----
__global__ __launch_bounds__(256) void gemm_qkv_h() {
    extern __shared__ __align__(16) char smem[];
    const uint32_t sb = smem_u32(smem);
    const int t = threadIdx.x, w = t >> 5, lane = t & 31;
    const int sub = lane >> 3, g = lane >> 2, tg = lane & 3;
    const int wr = w >> 1, wc = w & 1;
    const int m0 = blockIdx.y * 128, n0 = blockIdx.x * 128;

    const uint32_t a_off =
        ((wr * 32 + (sub & 1) * 8 + (lane & 7)) * GA_PITCH + (sub >> 1) * 8) * 2;
    const uint32_t b_off = GB_OFF +
        (((sub & 1) * 8 + (lane & 7)) * GB_PITCH + wc * 64 + (sub >> 1) * 8) * 2;

    const __half* Ag = g_seq_h + (size_t)m0 * 256;
    const int arow = t >> 1, acq = (t & 1) * 16;
    const int brow = t >> 3, bcq = (t & 7) * 16;

#define QKV_COPY(stg, kk)                                                      \
    do {                                                                       \
        uint32_t sbase = sb + (stg) * GST;                                     \
        cpa16(sbase + (arow * GA_PITCH + acq) * 2,                             \
              &Ag[arow * 256 + (kk) + acq]);                                   \
        cpa16(sbase + (arow * GA_PITCH + acq + 8) * 2,                         \
              &Ag[arow * 256 + (kk) + acq + 8]);                               \
        cpa16(sbase + GB_OFF + (brow * GB_PITCH + bcq) * 2,                    \
              &g_wq_h[((kk) + brow) * 768 + n0 + bcq]);                        \
        cpa16(sbase + GB_OFF + (brow * GB_PITCH + bcq + 8) * 2,                \
              &g_wq_h[((kk) + brow) * 768 + n0 + bcq + 8]);                    \
    } while (0)

    QKV_COPY(0, 0);
    CPA_COMMIT();

    float acc[2][8][4] = {};
    int cur = 0;
    for (int ki = 0; ki < 8; ki++) {
        int nxt = cur + 1; if (nxt == 3) nxt = 0;
        if (ki < 7) {
            QKV_COPY(nxt, (ki + 1) * 32);
            CPA_COMMIT();
            CPA_WAIT1();
        } else {
            CPA_WAIT0();
        }
        __syncthreads();
        const uint32_t abase = sb + cur * GST + a_off;
        const uint32_t bbase = sb + cur * GST + b_off;
#pragma unroll
        for (int ks = 0; ks < 2; ks++) {
            uint32_t a0[4], a1[4];
            ldsm4(a0, abase + ks * 32);
            ldsm4(a1, abase + 16 * GA_PITCH * 2 + ks * 32);
#pragma unroll
            for (int ntp = 0; ntp < 4; ntp++) {
                uint32_t vb[4];
                ldsm4t(vb, bbase + ks * 16 * GB_PITCH * 2 + ntp * 32);
                mma16(acc[0][2 * ntp],     a0, vb[0], vb[1]);
                mma16(acc[0][2 * ntp + 1], a0, vb[2], vb[3]);
                mma16(acc[1][2 * ntp],     a1, vb[0], vb[1]);
                mma16(acc[1][2 * ntp + 1], a1, vb[2], vb[3]);
            }
        }
        cur = nxt;
    }
#pragma unroll
    for (int mt = 0; mt < 2; mt++)
#pragma unroll
        for (int nt = 0; nt < 8; nt++) {
            int row = m0 + wr * 32 + mt * 16 + g;
            int col = n0 + wc * 64 + nt * 8 + 2 * tg;
            *(uint32_t*)&g_qkv_h[(size_t)row * 768 + col] =
                f2h2(acc[mt][nt][0], acc[mt][nt][1]);
            *(uint32_t*)&g_qkv_h[(size_t)(row + 8) * 768 + col] =
                f2h2(acc[mt][nt][2], acc[mt][nt][3]);
        }
}

// ---- Proj GEMM: (16384 x 256) @ (256 x 256) + b -> out NCHW, grid (2, 128) ----
__global__ __launch_bounds__(256) void gemm_proj_h(const float* __restrict__ bias,
                                                   float* __restrict__ out) {
    extern __shared__ __align__(16) char smem[];
    const uint32_t sb = smem_u32(smem);
    const int t = threadIdx.x, w = t >> 5, lane = t & 31;
    const int sub = lane >> 3, g = lane >> 2, tg = lane & 3;
    const int wr = w >> 1, wc = w & 1;
    const int m0 = blockIdx.y * 128, n0 = blockIdx.x * 128;

    const uint32_t a_off =
        ((wr * 32 + (sub & 1) * 8 + (lane & 7)) * GA_PITCH + (sub >> 1) * 8) * 2;
    const uint32_t b_off = GB_OFF +
        (((sub & 1) * 8 + (lane & 7)) * GB_PITCH + wc * 64 + (sub >> 1) * 8) * 2;

    const __half* Ag = g_o_h + (size_t)m0 * 256;
    const int arow = t >> 1, acq = (t & 1) * 16;
    const int brow = t >> 3, bcq = (t & 7) * 16;

#define PJ_COPY(stg, kk)                                                       \
    do {                                                                       \
        uint32_t sbase = sb + (stg) * GST;                                     \
        cpa16(sbase + (arow * GA_PITCH + acq) * 2,                             \
              &Ag[arow * 256 + (kk) + acq]);                                   \
        cpa16(sbase + (arow * GA_PITCH + acq + 8) * 2,                         \
              &Ag[arow * 256 + (kk) + acq + 8]);                               \
        cpa16(sbase + GB_OFF + (brow * GB_PITCH + bcq) * 2,                    \
              &g_wp_h[((kk) + brow) * 256 + n0 + bcq]);                        \
        cpa16(sbase + GB_OFF + (brow * GB_PITCH + bcq + 8) * 2,                \
              &g_wp_h[((kk) + brow) * 256 + n0 + bcq + 8]);                    \
    } while (0)

    PJ_COPY(0, 0);
    CPA_COMMIT();

    float acc[2][8][4] = {};
    int cur = 0;
    for (int ki = 0; ki < 8; ki++) {
        int nxt = cur + 1; if (nxt == 3) nxt = 0;
        if (ki < 7) {
            PJ_COPY(nxt, (ki + 1) * 32);
            CPA_COMMIT();
            CPA_WAIT1();
        } else {
            CPA_WAIT0();
        }
        __syncthreads();
        const uint32_t abase = sb + cur * GST + a_off;
        const uint32_t bbase = sb + cur * GST + b_off;
#pragma unroll
        for (int ks = 0; ks < 2; ks++) {
            uint32_t a0[4], a1[4];
            ldsm4(a0, abase + ks * 32);
            ldsm4(a1, abase + 16 * GA_PITCH * 2 + ks * 32);
#pragma unroll
            for (int ntp = 0; ntp < 4; ntp++) {
                uint32_t vb[4];
                ldsm4t(vb, bbase + ks * 16 * GB_PITCH * 2 + ntp * 32);
                mma16(acc[0][2 * ntp],     a0, vb[0], vb[1]);
                mma16(acc[0][2 * ntp + 1], a0, vb[2], vb[3]);
                mma16(acc[1][2 * ntp],     a1, vb[0], vb[1]);
                mma16(acc[1][2 * ntp + 1], a1, vb[2], vb[3]);
            }
        }
        cur = nxt;
    }
    __syncthreads();

    // stage [c][m+pad] fp32 for coalesced transposed store
    float* st = (float*)smem;
#pragma unroll
    for (int mt = 0; mt < 2; mt++)
#pragma unroll
        for (int nt = 0; nt < 8; nt++) {
            int rl = wr * 32 + mt * 16 + g;
            int cl = wc * 64 + nt * 8 + 2 * tg;
            st[cl * 132 + rl]           = acc[mt][nt][0];
            st[(cl + 1) * 132 + rl]     = acc[mt][nt][1];
            st[cl * 132 + rl + 8]       = acc[mt][nt][2];
            st[(cl + 1) * 132 + rl + 8] = acc[mt][nt][3];
        }
    __syncthreads();

    const int ml = t & 31, wi = t >> 5;
    const int nimg = m0 >> 12, pbase = m0 & 4095;
#pragma unroll
    for (int i = 0; i < 16; i++) {
        int cl = wi + 8 * i;
        float bb = bias[n0 + cl];
        float* orow = out + ((size_t)(nimg * C + n0 + cl)) * HW + pbase;
#pragma unroll
        for (int ch = 0; ch < 4; ch++)
            orow[ml + 32 * ch] = st[cl * 132 + ml + 32 * ch] + bb;
    }
}

// ===========================================================================
// fp16 flash attention (R13): q-tile 64, 2 warps (64 threads), 4 CTAs/SM.
// 3-stage cp.async K/V pipeline, register-resident P, S/exp/PV software
// pipeline, Q pre-scaled by 1/8.
// ===========================================================================
#define KV_STG   18432
#define SMEM_ATTN_B (3 * KV_STG)       // 55296 -> 4 CTAs/SM

__global__ __launch_bounds__(64, 4) void attn_mma() {
    extern __shared__ char smraw[];
    const uint32_t sb = smem_u32(smraw);

    const int t    = threadIdx.x;      // 0..63
    const int lane = t & 31;
    const int g    = lane >> 2;
    const int tg   = lane & 3;
    const int rb   = (t >> 5) * 32;

    const int qt = blockIdx.x;         // 0..63 (q-tiles of 64)
    const int nh = blockIdx.y;
    const int n  = nh >> 2, h = nh & 3;
    const __half* qkvh = g_qkv_h + (size_t)n * HW * THREE_C;

    const int rowl = t >> 3;          // copy row lane 0..7
    const int c8   = (t & 7) * 8;     // copy column (8 halfs = 16 B)

    const uint32_t sub = lane >> 3;
    const uint32_t kf_off = ((((sub >> 1) * 8) + (lane & 7)) * 72 + (sub & 1) * 8) * 2;
    const uint32_t vf_off = 9216 +
        ((((sub & 1) * 8) + (lane & 7)) * 72 + (sub >> 1) * 8) * 2;

#define ATTN_COPY(stg, kt_)                                                    \
    do {                                                                       \
        uint32_t sbase = sb + (stg) * KV_STG;                                  \
        _Pragma("unroll")                                                      \
        for (int i_ = 0; i_ < 8; i_++) {                                       \
            int row_ = rowl + 8 * i_;                                          \
            int rg_  = (kt_) * 64 + row_;                                      \
            int p_   = h * 1024 + (rg_ >> 2);                                  \
            int s_   = rg_ & 3;                                                \
            const __half* base_ = qkvh + (size_t)p_ * 768 + s_ * 192;          \
            cpa16(sbase + (row_ * 72 + c8) * 2, base_ + 64 + c8);              \
            cpa16(sbase + 9216 + (row_ * 72 + c8) * 2, base_ + 128 + c8);      \
        }                                                                      \
    } while (0)

    // Q A-frags in registers, pre-scaled by 1/8 (exact power of 2 in fp16)
    uint32_t aq[2][4][4];
    {
        const __half2 kEighth = __floats2half2_rn(0.125f, 0.125f);
#pragma unroll
        for (int mt = 0; mt < 2; mt++)
#pragma unroll
            for (int rr = 0; rr < 2; rr++) {
                int r  = qt * 64 + rb + mt * 16 + rr * 8 + g;
                int p  = h * 1024 + (r >> 2);
                int s  = r & 3;
                const __half* qrow = qkvh + (size_t)p * 768 + s * 192;
#pragma unroll
                for (int ks = 0; ks < 4; ks++) {
                    __half2 v0 = *(const __half2*)&qrow[ks * 16 + 2 * tg];
                    __half2 v1 = *(const __half2*)&qrow[ks * 16 + 8 + 2 * tg];
                    v0 = __hmul2(v0, kEighth);
                    v1 = __hmul2(v1, kEighth);
                    aq[mt][ks][rr]     = *(uint32_t*)&v0;
                    aq[mt][ks][rr + 2] = *(uint32_t*)&v1;
                }
            }
    }

    ATTN_COPY(0, 0);
    CPA_COMMIT();

    float co[2][8][4] = {};
    float lsum[2][2]  = {};

    int cur = 0;
    for (int kt = 0; kt < 64; kt++) {
        int nxt = cur + 1; if (nxt == 3) nxt = 0;
        if (kt < 63) {
            ATTN_COPY(nxt, kt + 1);
            CPA_COMMIT();
            CPA_WAIT1();
        } else {
            CPA_WAIT0();
        }
        __syncthreads();

        const uint32_t kfb = sb + cur * KV_STG + kf_off;
        const uint32_t vfb = sb + cur * KV_STG + vf_off;

        uint32_t pa[2][4][4];
        float s00[4], s01[4], s10[4], s11[4];

#define S_BLK(j)                                                               \
    do {                                                                       \
        _Pragma("unroll")                                                      \
        for (int i_ = 0; i_ < 4; i_++) {                                       \
            s00[i_] = 0.f; s01[i_] = 0.f; s10[i_] = 0.f; s11[i_] = 0.f;        \
        }                                                                      \
        _Pragma("unroll")                                                      \
        for (int ks_ = 0; ks_ < 4; ks_++) {                                    \
            uint32_t kb_[4];                                                   \
            ldsm4(kb_, kfb + (j) * 2304 + ks_ * 32);                           \
            mma16(s00, aq[0][ks_], kb_[0], kb_[1]);                            \
            mma16(s01, aq[0][ks_], kb_[2], kb_[3]);                            \
            mma16(s10, aq[1][ks_], kb_[0], kb_[1]);                            \
            mma16(s11, aq[1][ks_], kb_[2], kb_[3]);                            \
        }                                                                      \
    } while (0)

#define EXP_BLK(j)                                                             \
    do {                                                                       \
        float a0 = __expf(s00[0]), a1 = __expf(s00[1]);                        \
        float a2 = __expf(s00[2]), a3 = __expf(s00[3]);                        \
        float b0 = __expf(s01[0]), b1 = __expf(s01[1]);                        \
        float b2 = __expf(s01[2]), b3 = __expf(s01[3]);                        \
        lsum[0][0] += (a0 + a1) + (b0 + b1);                                   \
        lsum[0][1] += (a2 + a3) + (b2 + b3);                                   \
        pa[0][j][0] = f2h2(a0, a1);                                            \
        pa[0][j][1] = f2h2(a2, a3);                                            \
        pa[0][j][2] = f2h2(b0, b1);                                            \
        pa[0][j][3] = f2h2(b2, b3);                                            \
        float c0 = __expf(s10[0]), c1 = __expf(s10[1]);                        \
        float c2 = __expf(s10[2]), c3 = __expf(s10[3]);                        \
        float d0 = __expf(s11[0]), d1 = __expf(s11[1]);                        \
        float d2 = __expf(s11[2]), d3 = __expf(s11[3]);                        \
        lsum[1][0] += (c0 + c1) + (d0 + d1);                                   \
        lsum[1][1] += (c2 + c3) + (d2 + d3);                                   \
        pa[1][j][0] = f2h2(c0, c1);                                            \
        pa[1][j][1] = f2h2(c2, c3);                                            \
        pa[1][j][2] = f2h2(d0, d1);                                            \
        pa[1][j][3] = f2h2(d2, d3);                                            \
    } while (0)

#define PV_BLK(j)                                                              \
    do {                                                                       \
        _Pragma("unroll")                                                      \
        for (int ntp_ = 0; ntp_ < 4; ntp_++) {                                 \
            uint32_t vb_[4];                                                   \
            ldsm4t(vb_, vfb + (j) * 2304 + ntp_ * 32);                         \
            mma16(co[0][2 * ntp_],     pa[0][j], vb_[0], vb_[1]);              \
            mma16(co[0][2 * ntp_ + 1], pa[0][j], vb_[2], vb_[3]);              \
            mma16(co[1][2 * ntp_],     pa[1][j], vb_[0], vb_[1]);              \
            mma16(co[1][2 * ntp_ + 1], pa[1][j], vb_[2], vb_[3]);              \
        }                                                                      \
    } while (0)

        S_BLK(0); EXP_BLK(0);
        S_BLK(1); PV_BLK(0); EXP_BLK(1);
        S_BLK(2); PV_BLK(1); EXP_BLK(2);
        S_BLK(3); PV_BLK(2); EXP_BLK(3);
        PV_BLK(3);

        cur = nxt;
    }

    // finalize: quad row-sum reduce, normalize, stage as half, store
    float inv[2][2];
#pragma unroll
    for (int mt = 0; mt < 2; mt++)
#pragma unroll
        for (int hh = 0; hh < 2; hh++) {
            float l = lsum[mt][hh];
            l += __shfl_xor_sync(0xffffffffu, l, 1);
            l += __shfl_xor_sync(0xffffffffu, l, 2);
            inv[mt][hh] = 1.f / l;
        }
    __syncthreads();   // done with K/V smem; reuse as half staging [64][80]
#pragma unroll
    for (int mt = 0; mt < 2; mt++) {
        int r0 = rb + mt * 16 + g;
#pragma unroll
        for (int nt = 0; nt < 8; nt++) {
            *(uint32_t*)(smraw + (r0 * 80 + nt * 8 + 2 * tg) * 2) =
                f2h2(co[mt][nt][0] * inv[mt][0], co[mt][nt][1] * inv[mt][0]);
            *(uint32_t*)(smraw + ((r0 + 8) * 80 + nt * 8 + 2 * tg) * 2) =
                f2h2(co[mt][nt][2] * inv[mt][1], co[mt][nt][3] * inv[mt][1]);
        }
    }
    __syncthreads();
    {
        int rg = qt * 64 + t;
        int p  = h * 1024 + (rg >> 2);
        int s  = rg & 3;
        __half* dst = g_o_h + ((size_t)n * HW + p) * C + s * 64;
#pragma unroll
        for (int j = 0; j < 8; j++)
            *(uint4*)&dst[8 * j] = *(uint4*)(smraw + (t * 80 + 8 * j) * 2);
    }
}

// ---------------------------------------------------------------------------
// BatchNorm statistics (float4 loads) + fused weight conversion.
// Blocks [0, 256): per-channel BN stats. Blocks [256, 1280): weight convert.
// ---------------------------------------------------------------------------
__global__ void bn_stats_convert(const float* __restrict__ x,
                                 const float* __restrict__ gamma,
                                 const float* __restrict__ beta,
                                 const float* __restrict__ qkv_w,
                                 const float* __restrict__ proj_w) {
    int b = blockIdx.x;
    int t = threadIdx.x;
    if (b >= C) {
        int i = (b - C) * 256 + t;     // 0 .. 262143
        if (i < C * THREE_C)
            g_wq_h[i] = __float2half_rn(qkv_w[i]);
        else
            g_wp_h[i - C * THREE_C] = __float2half_rn(proj_w[i - C * THREE_C]);
        return;
    }
    int c = b;
    float s = 0.f, s2 = 0.f;
    for (int n = 0; n < N_IMG; n++) {
        const float4* p = (const float4*)(x + ((size_t)n * C + c) * HW);
        for (int i = t; i < HW / 4; i += 256) {
            float4 v = p[i];
            s  += (v.x + v.y) + (v.z + v.w);
            s2 += (v.x * v.x + v.y * v.y) + (v.z * v.z + v.w * v.w);
        }
    }
    __shared__ float sh0[256], sh1[256];
    sh0[t] = s; sh1[t] = s2;
    __syncthreads();
    for (int o = 128; o > 0; o >>= 1) {
        if (t < o) { sh0[t] += sh0[t + o]; sh1[t] += sh1[t + o]; }
        __syncthreads();
    }
    if (t == 0) {
        const float inv = 1.f / (float)(N_IMG * HW);
        float mean = sh0[0] * inv;
        float var  = sh1[0] * inv - mean * mean;
        float rstd = rsqrtf(var + 1e-5f);
        float sc   = gamma[c] * rstd;
        g_scale[c] = sc;
        g_shift[c] = beta[c] - mean * sc;
    }
}

// ---------------------------------------------------------------------------
// Normalize + transpose (n,c,hw) -> (n,hw,c) as half.
// 32 channels x 128 positions per block; float4 loads, uint4 stores.
// Pitch 133 smem: conflict-free in both phases.
// ---------------------------------------------------------------------------
__global__ __launch_bounds__(256) void norm_transpose(const float* __restrict__ x) {
    __shared__ float tile[32 * 133];
    int n  = blockIdx.z;
    int c0 = blockIdx.y * 32;
    int p0 = blockIdx.x * 128;
    int t  = threadIdx.x;              // 0..255
    int r  = t >> 3, q = t & 7;        // r: channel row 0..31, q: quad 0..7

    float sc = g_scale[c0 + r];
    float sh = g_shift[c0 + r];
    const float4* src = (const float4*)(x + ((size_t)n * C + c0 + r) * HW + p0);
#pragma unroll
    for (int it = 0; it < 4; it++) {
        float4 v = src[q + 8 * it];
        float* d = &tile[r * 133 + 4 * (q + 8 * it)];
        d[0] = v.x * sc + sh;
        d[1] = v.y * sc + sh;
        d[2] = v.z * sc + sh;
        d[3] = v.w * sc + sh;
    }
    __syncthreads();
#pragma unroll
    for (int it = 0; it < 2; it++) {
        int e   = it * 256 + t;        // 0..511
        int pos = e >> 2;              // 0..127
        int cg  = e & 3;               // channel group of 8
        uint32_t h0 = f2h2(tile[(8 * cg + 0) * 133 + pos], tile[(8 * cg + 1) * 133 + pos]);
        uint32_t h1 = f2h2(tile[(8 * cg + 2) * 133 + pos], tile[(8 * cg + 3) * 133 + pos]);
        uint32_t h2 = f2h2(tile[(8 * cg + 4) * 133 + pos], tile[(8 * cg + 5) * 133 + pos]);
        uint32_t h3 = f2h2(tile[(8 * cg + 6) * 133 + pos], tile[(8 * cg + 7) * 133 + pos]);
        *(uint4*)&g_seq_h[((size_t)n * HW + p0 + pos) * C + c0 + 8 * cg] =
            make_uint4(h0, h1, h2, h3);
    }
}

// ---------------------------------------------------------------------------
extern "C" void kernel_launch(void* const* d_in, const int* in_sizes, int n_in,
                              void* d_out, int out_size) {
    const float* x      = (const float*)d_in[0];
    const float* gamma  = (const float*)d_in[1];
    const float* beta   = (const float*)d_in[2];
    const float* qkv_w  = (const float*)d_in[3];
    const float* proj_w = (const float*)d_in[4];
    const float* proj_b = (const float*)d_in[5];
    float* out = (float*)d_out;

    cudaFuncSetAttribute(gemm_qkv_h,
                         cudaFuncAttributeMaxDynamicSharedMemorySize, QK_SMEM);
    cudaFuncSetAttribute(gemm_proj_h,
                         cudaFuncAttributeMaxDynamicSharedMemorySize, PJ_SMEM);
    cudaFuncSetAttribute(attn_mma,
                         cudaFuncAttributeMaxDynamicSharedMemorySize, SMEM_ATTN_B);

    bn_stats_convert<<<C + (C * THREE_C + C * C) / 256, 256>>>(
        x, gamma, beta, qkv_w, proj_w);
    norm_transpose<<<dim3(32, 8, 4), 256>>>(x);
    gemm_qkv_h<<<dim3(6, 128), 256, QK_SMEM>>>();
    attn_mma<<<dim3(64, 16), 64, SMEM_ATTN_B>>>();
    gemm_proj_h<<<dim3(2, 128), 256, PJ_SMEM>>>(proj_b, out);
}